// round 16
// baseline (speedup 1.0000x reference)
#include <cuda_runtime.h>
#include <cuda_bf16.h>

#define BB 4
#define TT 512
#define VV 8000
#define HH 7
#define VP 8192          // padded vocab stride
#define GUARD_TH 4e-3f

// Scratch (allocation-free rule: __device__ globals)
__device__ float g_vocab[3][HH][VP];   // [0]=angle, [1]=sqrt2*A/h^d*sin, [2]=sqrt2*A/h^d*cos
__device__ float g_C[BB * TT * VV];    // 65.5 MB
__device__ int   g_pad_sink;

__device__ __forceinline__ float frcp(float x) {
    float d;
    asm("rcp.approx.f32 %0, %1;" : "=f"(d) : "f"(x));
    return d;
}

// ---------------------------------------------------------------------------
// Kernel A: per-vocab harmonic tables; sqrt(2) baked into both trig entries
// so any product of two trig entries carries the final 2.0 factor.
// ---------------------------------------------------------------------------
__global__ void build_tables(const float* __restrict__ freq,
                             const float* __restrict__ amp,
                             const float* __restrict__ decay) {
    int v = blockIdx.x * blockDim.x + threadIdx.x;
    if (v >= VV) return;
    float f   = freq[v];
    float A   = amp[v];
    float dec = decay[0];
    const float TWO_PI = 6.2831853071795864769f;
    const float SQRT2  = 1.4142135623730951f;
#pragma unroll
    for (int j = 0; j < HH; j++) {
        float h   = (float)(j + 1);
        float ang = TWO_PI * f * h;
        float Ah  = SQRT2 * A / powf(h, dec);
        float s, c;
        sincosf(ang, &s, &c);
        g_vocab[0][j][v] = ang;
        g_vocab[1][j][v] = Ah * s;
        g_vocab[2][j][v] = Ah * c;
    }
}

// ---------------------------------------------------------------------------
// Kernel B (single merged launch, grid (v-tiles, t-tiles, B)):
// batch-2 reciprocal form. Per j-pair:
//   vcs0/r0 + vcs1/r1 = num1 * inv,  inv = 1/(r0*r1)
//   num1 = fma(a, cS1, cM1)  (precomputed per-v constants; precision-safe)
// Guard: pair product |p| vs P_th = th*|b1|+th^2 (covers |r0|<th or |r1|<th,
// safe at f_v -> 0), scalar j6 on |r|. 28 FMNMX/ttl instead of 49.
// Rare exact recompute per (thread,ttl) on guard fire.
// ---------------------------------------------------------------------------
__global__ void __launch_bounds__(256) wave_C(const int* __restrict__ ids) {
    __shared__ float sA[16][HH];
    __shared__ float sS[16][HH];
    __shared__ float sC[16][HH];
    __shared__ int   sid[16];

    const int b   = blockIdx.z;
    const int t0  = blockIdx.y * 16;
    const int tid = threadIdx.x;

    if (tid < 16) sid[tid] = ids[b * TT + t0 + tid];
    __syncthreads();
    if (tid < 16 * HH) {                 // 112 (tt,i) pairs
        int ttl = tid / HH, i = tid % HH;
        int u   = sid[ttl];
        sA[ttl][i] = g_vocab[0][i][u];
        sS[ttl][i] = g_vocab[1][i][u];
        sC[ttl][i] = g_vocab[2][i][u];
    }
    __syncthreads();

    const int v  = blockIdx.x * 256 + tid;
    const int vc = (v < VV) ? v : (VV - 1);
    const bool ok = (v < VV);

    // Per-v pair constants: jp pairs (0,1),(2,3),(4,5); scalar j=6.
    float nb0[3], nb1[3], cS1[3], cM1[3], cS2[3], cM2[3];
#pragma unroll
    for (int jp = 0; jp < 3; jp++) {
        int j0 = 2 * jp, j1 = 2 * jp + 1;
        float b0 = g_vocab[0][j0][vc], b1 = g_vocab[0][j1][vc];
        float c0 = g_vocab[2][j0][vc], c1 = g_vocab[2][j1][vc];
        float s0 = g_vocab[1][j0][vc], s1 = g_vocab[1][j1][vc];
        nb0[jp] = -b0;
        nb1[jp] = -b1;
        cS1[jp] = c0 + c1;                       // S1 (cos side)
        cM1[jp] = -fmaf(c0, b1, c1 * b0);
        cS2[jp] = -(s0 + s1);                    // S2 (neg-sin side)
        cM2[jp] = fmaf(s0, b1, s1 * b0);
    }
    const float nb6  = -g_vocab[0][6][vc];
    const float vcs6 =  g_vocab[2][6][vc];
    const float nvs6 = -g_vocab[1][6][vc];

    // Pair-product guard threshold: adjacent-root spacing |Delta| = |b1| = 2*pi*|f_v|.
    // |r0|<th or |r1|<th  =>  |r0*r1| < th*(|Delta|+th) = P_th.  Safe at f_v=0 (-> th^2).
    const float P_th = fmaf(GUARD_TH, fabsf(nb0[0]), GUARD_TH * GUARD_TH);

#pragma unroll 1                         // keep bodies in I$ once
    for (int ttl = 0; ttl < 16; ttl++) {
        float acc = 0.0f;
        float mp  = 1e30f;   // min |r0*r1| over pairs
        float mr  = 1e30f;   // min |r| over scalar j6
#pragma unroll
        for (int i = 0; i < HH; i++) {
            const float a  = sA[ttl][i];
            const float sa = sS[ttl][i];
            const float ca = sC[ttl][i];
            float S1 = 0.0f, S2 = 0.0f;
#pragma unroll
            for (int jp = 0; jp < 3; jp++) {
                float r0 = a + nb0[jp];
                float r1 = a + nb1[jp];
                float p   = r0 * r1;
                mp = fminf(mp, fabsf(p));
                float inv = frcp(p);
                float n1  = fmaf(a, cS1[jp], cM1[jp]);
                float n2  = fmaf(a, cS2[jp], cM2[jp]);
                S1 = fmaf(n1, inv, S1);
                S2 = fmaf(n2, inv, S2);
            }
            {   // scalar j = 6
                float r = a + nb6;
                mr = fminf(mr, fabsf(r));
                float d = frcp(r);
                S1 = fmaf(vcs6, d, S1);
                S2 = fmaf(nvs6, d, S2);
            }
            acc = fmaf(sa, S1, acc);
            acc = fmaf(ca, S2, acc);
        }
        if (mp < P_th || mr < GUARD_TH) {
            // Rare exact recompute (R1-validated math; cold LDG reloads).
            acc = 0.0f;
#pragma unroll 1
            for (int i = 0; i < HH; i++) {
                float a  = sA[ttl][i];
                float sa = sS[ttl][i];
                float ca = sC[ttl][i];
#pragma unroll
                for (int j = 0; j < HH; j++) {
                    float bj  = g_vocab[0][j][vc];
                    float vsj = g_vocab[1][j][vc];
                    float vcj = g_vocab[2][j][vc];
                    float r   = a - bj;
                    float d   = frcp(r);
                    float num = fmaf(sa, vcj, -(ca * vsj));  // 2AA*sin(r)
                    float val = num * d;
                    float alt = fmaf(sa, vsj, ca * vcj);     // 2AA*cos(r) ~ limit
                    acc += (fabsf(r) < GUARD_TH) ? alt : val;
                }
            }
        }
        if (ok) g_C[(size_t)((b * TT + t0 + ttl)) * VV + v] = acc;
    }
}

// ---------------------------------------------------------------------------
// Kernel C: exclusive cumsum over t per (b,v) column; 8-wide load batching
// ---------------------------------------------------------------------------
__global__ void __launch_bounds__(256) cumshift(float* __restrict__ out) {
    int idx = blockIdx.x * blockDim.x + threadIdx.x;
    if (idx >= BB * VV) return;
    int b = idx / VV;
    int v = idx - b * VV;
    const float* crow = g_C + (size_t)b * TT * VV + v;
    float*       orow = out + (size_t)b * TT * VV + v;
    float run = 0.0f;
#pragma unroll 1
    for (int t = 0; t < TT; t += 8) {
        float x[8];
#pragma unroll
        for (int k = 0; k < 8; k++) x[k] = crow[(size_t)(t + k) * VV];
#pragma unroll
        for (int k = 0; k < 8; k++) { orow[(size_t)(t + k) * VV] = run; run += x[k]; }
    }
}

// Pad kernel: launch cycle length 4 to help ncu (-s 5 -c 1) land on wave_C.
__global__ void pad_k() { if (threadIdx.x == 0) g_pad_sink = 1; }

// ---------------------------------------------------------------------------
extern "C" void kernel_launch(void* const* d_in, const int* in_sizes, int n_in,
                              void* d_out, int out_size) {
    const int*   ids   = (const int*)d_in[0];
    const float* freq  = (const float*)d_in[1];
    const float* amp   = (const float*)d_in[2];
    const float* decay = (const float*)d_in[3];
    // d_in[4] = chunk_size: result independent of chunking; ignored.

    build_tables<<<(VV + 255) / 256, 256>>>(freq, amp, decay);

    // Single merged launch: 4096 blocks -> ~6 full scheduling rounds per SM,
    // removing the 1.38-wave tail each of the 4 split launches paid.
    dim3 gridB((VV + 255) / 256, TT / 16, BB);
    wave_C<<<gridB, 256>>>(ids);

    cumshift<<<(BB * VV + 255) / 256, 256>>>((float*)d_out);

    pad_k<<<1, 32>>>();
}